// round 8
// baseline (speedup 1.0000x reference)
#include <cuda_runtime.h>
#include <cuda_fp16.h>
#include <math.h>
#include <stdint.h>

#define NN 50000
#define NE 800000
#define FI 128
#define FH 256
#define K1 25000
#define K2 12500
#define NSCAN 49  // ceil(NN/1024)

// ---------------- scratch (device globals; zero-init, allocation-free) -----
__device__ __align__(16) float g_xa[NN * FH];    // L5 gemm out
__device__ __align__(16) float g_h[NN * FH];     // L0 gemm out
__device__ __align__(16) float g_hid0[NN * FH];  // L1 out (full)
__device__ __align__(16) float g_hid1[NN * FH];  // L2 out (scattered; else 0)
__device__ __align__(16) float g_hbot[NN * FH];  // L3 out (scattered; else 0)
__device__ __align__(16) float g_h4[NN * FH];    // L4 out (scattered; else 0)
__device__ __align__(16) __half g_xh[NN * FH];   // gemm A hi (L0 only now)
__device__ __align__(16) __half g_xl[NN * FH];   // gemm A lo
__device__ __align__(16) __half g_wth[327680];   // weights hi (transposed)
__device__ __align__(16) __half g_wtl[327680];   // weights lo
__device__ int g_degout[NN];
__device__ int g_degO1[NN], g_degI1[NN], g_degO2[NN], g_degI2[NN];
__device__ float g_comb1[NN], g_dov1[NN], g_div1[NN];
__device__ float g_comb2[NN], g_dov2[NN], g_div2[NN];
__device__ float g_scores[NN];
__device__ unsigned g_keys[NN];
__device__ int g_rowstart[NN + 1];
__device__ int g_rowoff[NN];
__device__ int g_csrsrc[NE];
__device__ int g_alist1[NN], g_alist2[NN];
__device__ int g_nact[2];
__device__ unsigned g_prefix;
__device__ int g_bsum[64];

#define WO_EMB  0
#define WO_ENC0 32768
#define WO_ENC1 98304
#define WO_BOT  163840
#define WO_DEC0 229376
#define WO_DEC1 294912

__device__ __forceinline__ unsigned f2k(float f) {
    unsigned u = __float_as_uint(f);
    return (u & 0x80000000u) ? ~u : (u | 0x80000000u);
}
__device__ __forceinline__ void split4(float4 v, __half2* ph, __half2* pl) {
    __half h0 = __float2half_rn(v.x), h1 = __float2half_rn(v.y);
    __half h2 = __float2half_rn(v.z), h3 = __float2half_rn(v.w);
    __half l0 = __float2half_rn(v.x - __half2float(h0));
    __half l1 = __float2half_rn(v.y - __half2float(h1));
    __half l2 = __float2half_rn(v.z - __half2float(h2));
    __half l3 = __float2half_rn(v.w - __half2float(h3));
    ph[0] = __halves2half2(h0, h1); ph[1] = __halves2half2(h2, h3);
    pl[0] = __halves2half2(l0, l1); pl[1] = __halves2half2(l2, l3);
}

// ---------------- prep ----------------
__global__ void prep_kernel(const float* __restrict__ We, const float* __restrict__ W0,
                            const float* __restrict__ W1, const float* __restrict__ Wb,
                            const float* __restrict__ Wd0, const float* __restrict__ Wd1) {
    int i = blockIdx.x * blockDim.x + threadIdx.x;
    if (i < NN) {
        g_rowoff[i] = 0; g_degout[i] = 0;
        g_degO1[i] = 0; g_degI1[i] = 0;
        g_degO2[i] = 0; g_degI2[i] = 0;
    }
    if (i == 0) { g_nact[0] = 0; g_nact[1] = 0; g_rowstart[NN] = NE; }
    float w; int o;
    if (i < 32768) {
        int k = i >> 8, n = i & 255;
        w = We[i]; o = WO_EMB + n * 128 + k;
    } else if (i < 98304) {
        int j = i - 32768; int k = j >> 8, n = j & 255;
        w = W0[j]; o = WO_ENC0 + n * 256 + k;
    } else if (i < 163840) {
        int j = i - 98304; int k = j >> 8, n = j & 255;
        w = W1[j]; o = WO_ENC1 + n * 256 + k;
    } else if (i < 229376) {
        int j = i - 163840; int k = j >> 8, n = j & 255;
        w = Wb[j]; o = WO_BOT + n * 256 + k;
    } else if (i < 294912) {
        int j = i - 229376; int k = j >> 8, n = j & 255;
        w = Wd0[j]; o = WO_DEC0 + n * 256 + k;
    } else if (i < 327680) {
        int j = i - 294912; int k = j >> 7, n = j & 127;
        w = Wd1[j]; o = WO_DEC1 + n * 256 + k;
    } else return;
    __half h = __float2half_rn(w);
    g_wth[o] = h;
    g_wtl[o] = __float2half_rn(w - __half2float(h));
}

// ---------------- CSR build ----------------
__global__ void hist_kernel(const int* __restrict__ src, const int* __restrict__ dst) {
    int e = blockIdx.x * blockDim.x + threadIdx.x;
    if (e < NE) {
        atomicAdd(&g_rowoff[dst[e]], 1);
        atomicAdd(&g_degout[src[e]], 1);
    }
}
__global__ void scan1_kernel() {
    int b = blockIdx.x, t = threadIdx.x;
    int i = b * 1024 + t;
    int v = (i < NN) ? g_rowoff[i] : 0;
    int lane = t & 31, wid = t >> 5;
    int x = v;
#pragma unroll
    for (int off = 1; off < 32; off <<= 1) {
        int y = __shfl_up_sync(0xFFFFFFFFu, x, off);
        if (lane >= off) x += y;
    }
    __shared__ int ws[32];
    if (lane == 31) ws[wid] = x;
    __syncthreads();
    if (wid == 0) {
        int y = ws[lane];
#pragma unroll
        for (int off = 1; off < 32; off <<= 1) {
            int z = __shfl_up_sync(0xFFFFFFFFu, y, off);
            if (lane >= off) y += z;
        }
        ws[lane] = y;
    }
    __syncthreads();
    int base = wid ? ws[wid - 1] : 0;
    if (i < NN) g_rowstart[i] = base + x - v;
    if (t == 1023) g_bsum[b] = base + x;
}
__global__ void scan3_kernel() {
    __shared__ int boff[NSCAN + 1];
    int t = threadIdx.x;
    if (t < NSCAN) boff[t + 1] = g_bsum[t];
    __syncthreads();
    if (t == 0) {
        boff[0] = 0;
        for (int b = 1; b <= NSCAN; b++) boff[b] += boff[b - 1];
    }
    __syncthreads();
    int i = blockIdx.x * blockDim.x + t;
    if (i < NN) {
        int rs = g_rowstart[i] + boff[i >> 10];
        g_rowstart[i] = rs;
        g_rowoff[i] = rs;
    }
}
__global__ void scatter_kernel(const int* __restrict__ src, const int* __restrict__ dst) {
    int e = blockIdx.x * blockDim.x + threadIdx.x;
    if (e < NE) {
        int pos = atomicAdd(&g_rowoff[dst[e]], 1);
        g_csrsrc[pos] = src[e];
    }
}

// ---------------- standalone CSR aggregation (L0, F=128) ----------------
__global__ void agg_half_kernel(const float* __restrict__ x, const int* __restrict__ degsrc,
                                __half* __restrict__ oh, __half* __restrict__ ol) {
    int wid = (blockIdx.x * blockDim.x + threadIdx.x) >> 5;
    if (wid >= NN) return;
    int lane = threadIdx.x & 31;
    int s = g_rowstart[wid], e = g_rowstart[wid + 1];
    float4 a0 = make_float4(0.f, 0.f, 0.f, 0.f);
    for (int b = s; b < e; b += 32) {
        int nn = min(32, e - b);
        int si = 0; float sc = 0.f;
        if (lane < nn) {
            si = g_csrsrc[b + lane];
            sc = rsqrtf((float)max(degsrc[si], 1));
        }
        for (int k = 0; k < nn; k++) {
            int sik = __shfl_sync(0xFFFFFFFFu, si, k);
            float sck = __shfl_sync(0xFFFFFFFFu, sc, k);
            float4 v = ((const float4*)x)[(size_t)sik * 32 + lane];
            a0.x = fmaf(v.x, sck, a0.x); a0.y = fmaf(v.y, sck, a0.y);
            a0.z = fmaf(v.z, sck, a0.z); a0.w = fmaf(v.w, sck, a0.w);
        }
    }
    float dv = rsqrtf((float)max(e - s, 1));
    a0.x *= dv; a0.y *= dv; a0.z *= dv; a0.w *= dv;
    size_t o = (size_t)wid * FI + lane * 4;
    split4(a0, (__half2*)(oh + o), (__half2*)(ol + o));
}

__global__ void agg_out_kernel(const float* __restrict__ x, const float* __restrict__ bias,
                               float* __restrict__ out) {
    int wid = (blockIdx.x * blockDim.x + threadIdx.x) >> 5;
    if (wid >= NN) return;
    int lane = threadIdx.x & 31;
    int s = g_rowstart[wid], e = g_rowstart[wid + 1];
    float4 acc = make_float4(0.f, 0.f, 0.f, 0.f);
    for (int b = s; b < e; b += 32) {
        int nn = min(32, e - b);
        int si = 0;
        if (lane < nn) si = g_csrsrc[b + lane];
        for (int k = 0; k < nn; k++) {
            int sik = __shfl_sync(0xFFFFFFFFu, si, k);
            float4 v = ((const float4*)x)[(size_t)sik * 32 + lane];
            acc.x += v.x; acc.y += v.y; acc.z += v.z; acc.w += v.w;
        }
    }
    float dv = rsqrtf((float)max(e - s, 1));
    float4 bb = ((const float4*)bias)[lane];
    acc.x = fmaf(acc.x, dv, bb.x); acc.y = fmaf(acc.y, dv, bb.y);
    acc.z = fmaf(acc.z, dv, bb.z); acc.w = fmaf(acc.w, dv, bb.w);
    ((float4*)out)[(size_t)wid * 32 + lane] = acc;
}

// ---------------- HMMA fp16-split GEMM core (ldmatrix) ----------------
#define SMS 72
#define STAGE_HALFS (4 * 128 * SMS)
#define GEMM_SMEM_DB (2 * STAGE_HALFS * 2)
#define GEMM_SMEM_SB (STAGE_HALFS * 2)
// fused: A = 4 chunks x (2 x 128 x SMS) halves ; B = 2 x 256 x SMS halves
#define FUSED_ACH (2 * 128 * SMS)
#define FUSED_A_TOTAL (4 * FUSED_ACH)
#define FUSED_SMEM ((FUSED_A_TOTAL + 2 * 256 * SMS) * 2)

#define MMA168(d, a, b) \
    asm volatile( \
        "mma.sync.aligned.m16n8k16.row.col.f32.f16.f16.f32 " \
        "{%0,%1,%2,%3}, {%4,%5,%6,%7}, {%8,%9}, {%0,%1,%2,%3};" \
        : "+f"((d)[0]), "+f"((d)[1]), "+f"((d)[2]), "+f"((d)[3]) \
        : "r"((a)[0]), "r"((a)[1]), "r"((a)[2]), "r"((a)[3]), \
          "r"((b)[0]), "r"((b)[1]))

__device__ __forceinline__ void ldsm4(uint32_t addr, uint32_t* r) {
    asm volatile("ldmatrix.sync.aligned.m8n8.x4.shared.b16 {%0,%1,%2,%3}, [%4];"
                 : "=r"(r[0]), "=r"(r[1]), "=r"(r[2]), "=r"(r[3]) : "r"(addr));
}
__device__ __forceinline__ void cpa16(uint32_t dst, const void* src, int srcsz) {
    asm volatile("cp.async.cg.shared.global [%0], [%1], 16, %2;"
                 :: "r"(dst), "l"(src), "r"(srcsz) : "memory");
}

// one 64-wide K chunk. aBase: bytes addr of A chunk (hi at 0, lo at +128*SMS*2).
// bBase: bytes addr of B chunk hi; lo at +bHalfOff bytes.
__device__ __forceinline__ void compute_chunk(uint32_t aBase, uint32_t bBase, uint32_t bHalfOff,
                                              int wm, int wn, int lane, float acc[4][4][4]) {
    const uint32_t bAh = aBase;
    const uint32_t bAl = aBase + 128 * SMS * 2;
    const uint32_t bBh = bBase;
    const uint32_t bBl = bBase + bHalfOff;
    uint32_t aOff = (uint32_t)((wm + (lane & 15)) * SMS + (lane >> 4) * 8) * 2;
    uint32_t bOff = (uint32_t)((wn + ((lane >> 4) & 1) * 8 + (lane & 7)) * SMS +
                               ((lane >> 3) & 1) * 8) * 2;
#pragma unroll
    for (int ks = 0; ks < 4; ks++) {
        uint32_t kb2 = (uint32_t)ks * 32;
        uint32_t ar[4][4], br[4][2], bl[4][2];
#pragma unroll
        for (int mi = 0; mi < 4; mi++)
            ldsm4(bAh + aOff + mi * (16 * SMS * 2) + kb2, ar[mi]);
#pragma unroll
        for (int p = 0; p < 2; p++) {
            uint32_t r4[4];
            ldsm4(bBh + bOff + p * (16 * SMS * 2) + kb2, r4);
            br[2 * p][0] = r4[0]; br[2 * p][1] = r4[1];
            br[2 * p + 1][0] = r4[2]; br[2 * p + 1][1] = r4[3];
            ldsm4(bBl + bOff + p * (16 * SMS * 2) + kb2, r4);
            bl[2 * p][0] = r4[0]; bl[2 * p][1] = r4[1];
            bl[2 * p + 1][0] = r4[2]; bl[2 * p + 1][1] = r4[3];
        }
#pragma unroll
        for (int mi = 0; mi < 4; mi++)
#pragma unroll
            for (int ni = 0; ni < 4; ni++) {
                MMA168(acc[mi][ni], ar[mi], br[ni]);
                MMA168(acc[mi][ni], ar[mi], bl[ni]);
            }
#pragma unroll
        for (int mi = 0; mi < 4; mi++)
            ldsm4(bAl + aOff + mi * (16 * SMS * 2) + kb2, ar[mi]);
#pragma unroll
        for (int mi = 0; mi < 4; mi++)
#pragma unroll
            for (int ni = 0; ni < 4; ni++)
                MMA168(acc[mi][ni], ar[mi], br[ni]);
    }
}

__device__ __forceinline__ void gemm_epilogue(float acc[4][4][4], float* C, int M, int N,
                                              int m0, int n0, int wm, int wn, int g, int tig,
                                              const int* alist, const float* bias,
                                              const int* degrm, int act) {
#pragma unroll
    for (int mi = 0; mi < 4; mi++) {
#pragma unroll
        for (int half8 = 0; half8 < 2; half8++) {
            int lrow = m0 + wm + mi * 16 + g + half8 * 8;
            if (lrow >= M) continue;
            int grow = alist ? alist[lrow] : lrow;
            float rm = degrm ? rsqrtf((float)max(degrm[grow], 1)) : 1.f;
#pragma unroll
            for (int ni = 0; ni < 4; ni++) {
                int col = n0 + wn + ni * 8 + tig * 2;
                float v0 = acc[mi][ni][half8 * 2 + 0];
                float v1 = acc[mi][ni][half8 * 2 + 1];
                if (bias) { v0 += bias[col]; v1 += bias[col + 1]; }
                if (act) { v0 = fmaxf(v0, 0.f); v1 = fmaxf(v1, 0.f); }
                v0 *= rm; v1 *= rm;
                *(float2*)(C + (size_t)grow * N + col) = make_float2(v0, v1);
            }
        }
    }
}

// ---------------- FUSED agg + GEMM (K=256, N=256) ----------------
// Each block: gather+normalize 128 node rows -> smem fp16 split A, then
// 128x256x256 3-pass HMMA, epilogue bias/relu/scatter.
__global__ void __launch_bounds__(512, 1)
fused_kernel(const float* __restrict__ x, const float* __restrict__ x2,
             const float* __restrict__ smul, const int* __restrict__ degsrc,
             const float* __restrict__ divv, const int* __restrict__ alist,
             const __half* __restrict__ Bh, const __half* __restrict__ Bl,
             float* __restrict__ C, int M, const float* __restrict__ bias, int act) {
    extern __shared__ __half sm[];
    uint32_t smbase = (uint32_t)__cvta_generic_to_shared(sm);
    int t = threadIdx.x, w = t >> 5, lane = t & 31;
    int m0 = blockIdx.x * 128;

    // ---- agg phase: warp w -> local rows w*8 .. w*8+7
    for (int i = 0; i < 8; i++) {
        int lrow = w * 8 + i;
        int grow = m0 + lrow;
        float4 a0 = make_float4(0.f, 0.f, 0.f, 0.f);
        float4 a1 = make_float4(0.f, 0.f, 0.f, 0.f);
        float dv = 0.f;
        if (grow < M) {
            int node = alist ? alist[grow] : grow;
            int s = g_rowstart[node], e = g_rowstart[node + 1];
            for (int b = s; b < e; b += 32) {
                int nn = min(32, e - b);
                int si = 0; float sc = 0.f;
                if (lane < nn) {
                    si = g_csrsrc[b + lane];
                    if (smul) sc = smul[si];
                    else if (degsrc) sc = rsqrtf((float)max(degsrc[si], 1));
                    else sc = 1.f;
                }
                for (int k = 0; k < nn; k++) {
                    int sik = __shfl_sync(0xFFFFFFFFu, si, k);
                    float sck = __shfl_sync(0xFFFFFFFFu, sc, k);
                    if (sck != 0.f) {
                        const float4* xp = (const float4*)x + (size_t)sik * 64 + lane;
                        float4 v = xp[0];
                        float4 v1 = xp[32];
                        if (x2) {
                            const float4* yp = (const float4*)x2 + (size_t)sik * 64 + lane;
                            float4 u = yp[0], u1 = yp[32];
                            v.x += u.x; v.y += u.y; v.z += u.z; v.w += u.w;
                            v1.x += u1.x; v1.y += u1.y; v1.z += u1.z; v1.w += u1.w;
                        }
                        a0.x = fmaf(v.x, sck, a0.x); a0.y = fmaf(v.y, sck, a0.y);
                        a0.z = fmaf(v.z, sck, a0.z); a0.w = fmaf(v.w, sck, a0.w);
                        a1.x = fmaf(v1.x, sck, a1.x); a1.y = fmaf(v1.y, sck, a1.y);
                        a1.z = fmaf(v1.z, sck, a1.z); a1.w = fmaf(v1.w, sck, a1.w);
                    }
                }
            }
            dv = divv ? divv[node] : rsqrtf((float)max(e - s, 1));
        }
        a0.x *= dv; a0.y *= dv; a0.z *= dv; a0.w *= dv;
        a1.x *= dv; a1.y *= dv; a1.z *= dv; a1.w *= dv;
        // chunked smem write: k0 = lane*4 (chunk k0>>6), k1 = 128 + lane*4
        int k0 = lane * 4, c0 = k0 >> 6, o0 = k0 & 63;
        int k1 = 128 + lane * 4, c1 = k1 >> 6, o1 = k1 & 63;
        split4(a0, (__half2*)(sm + c0 * FUSED_ACH + lrow * SMS + o0),
                   (__half2*)(sm + c0 * FUSED_ACH + 128 * SMS + lrow * SMS + o0));
        split4(a1, (__half2*)(sm + c1 * FUSED_ACH + lrow * SMS + o1),
                   (__half2*)(sm + c1 * FUSED_ACH + 128 * SMS + lrow * SMS + o1));
    }
    __syncthreads();

    // ---- gemm phase
    int g = lane >> 2, tig = lane & 3;
    int wm = (w & 1) * 64, wn = (w >> 1) * 32;  // w in 0..15 -> wn 0..224
    float acc[4][4][4];
#pragma unroll
    for (int i = 0; i < 4; i++)
#pragma unroll
        for (int j = 0; j < 4; j++)
#pragma unroll
            for (int k = 0; k < 4; k++) acc[i][j][k] = 0.f;

    for (int c = 0; c < 4; c++) {
        // load B chunk: 2 halves x 256 rows x 64 halfs = 4096 uint4
        for (int idx = t; idx < 4096; idx += 512) {
            int arr = idx >> 11, j = idx & 2047, r = j >> 3, cc = j & 7;
            const __half* gp = (arr ? Bl : Bh) + (size_t)r * 256 + c * 64 + cc * 8;
            *(uint4*)(sm + FUSED_A_TOTAL + arr * 256 * SMS + r * SMS + cc * 8) =
                *(const uint4*)gp;
        }
        __syncthreads();
        compute_chunk(smbase + (uint32_t)(c * FUSED_ACH) * 2,
                      smbase + (uint32_t)FUSED_A_TOTAL * 2,
                      (uint32_t)(256 * SMS) * 2, wm, wn, lane, acc);
        __syncthreads();
    }
    gemm_epilogue(acc, C, M, 256, m0, 0, wm, wn, g, tig, alist, bias, nullptr, act);
}

// double-buffered cp.async GEMM (L0): A pre-split (Ah/Al), N=256
__global__ void __launch_bounds__(256, 1)
gemm_db_kernel(const __half* __restrict__ Ah, const __half* __restrict__ Al,
               const __half* __restrict__ Bh, const __half* __restrict__ Bl,
               float* __restrict__ C, int M, int K, int N,
               const float* __restrict__ bias, int act) {
    extern __shared__ __half sm[];
    uint32_t smbase = (uint32_t)__cvta_generic_to_shared(sm);
    int t = threadIdx.x;
    int m0 = blockIdx.y * 128, n0 = blockIdx.x * 128;
    int w = t >> 5, lane = t & 31;
    int g = lane >> 2, tig = lane & 3;
    int wm = (w & 1) * 64, wn = (w >> 1) * 32;

    float acc[4][4][4];
#pragma unroll
    for (int i = 0; i < 4; i++)
#pragma unroll
        for (int j = 0; j < 4; j++)
#pragma unroll
            for (int k = 0; k < 4; k++) acc[i][j][k] = 0.f;

    auto issue = [&](int st, int kc) {
        uint32_t sb = smbase + (uint32_t)st * (STAGE_HALFS * 2);
        for (int idx = t; idx < 2048; idx += 256) {
            int arr = idx >> 10, j = idx & 1023, r = j >> 3, c = j & 7;
            const __half* gp = (arr ? Al : Ah) + (size_t)(m0 + r) * K + kc + c * 8;
            int sz = (m0 + r < M) ? 16 : 0;
            cpa16(sb + (uint32_t)(arr * 128 * SMS + r * SMS + c * 8) * 2, gp, sz);
        }
        for (int idx = t; idx < 2048; idx += 256) {
            int arr = idx >> 10, j = idx & 1023, r = j >> 3, c = j & 7;
            const __half* gp = (arr ? Bl : Bh) + (size_t)(n0 + r) * K + kc + c * 8;
            cpa16(sb + (uint32_t)(256 * SMS + arr * 128 * SMS + r * SMS + c * 8) * 2, gp, 16);
        }
        asm volatile("cp.async.commit_group;" ::: "memory");
    };

    int nch = K >> 6;
    issue(0, 0);
    for (int c = 0; c < nch; c++) {
        int st = c & 1;
        if (c + 1 < nch) {
            issue(st ^ 1, (c + 1) << 6);
            asm volatile("cp.async.wait_group 1;" ::: "memory");
        } else {
            asm volatile("cp.async.wait_group 0;" ::: "memory");
        }
        __syncthreads();
        uint32_t sb = smbase + (uint32_t)st * (STAGE_HALFS * 2);
        compute_chunk(sb, sb + (uint32_t)(256 * SMS) * 2, (uint32_t)(128 * SMS) * 2,
                      wm, wn, lane, acc);
        __syncthreads();
    }
    gemm_epilogue(acc, C, M, N, m0, n0, wm, wn, g, tig, nullptr, bias, nullptr, act);
}

// single-buffer GEMM with fused fp32 add + split on load (L5): N=128
__global__ void __launch_bounds__(256, 2)
gemm_sb_kernel(const float* __restrict__ A0, const float* __restrict__ A1,
               const __half* __restrict__ Bh, const __half* __restrict__ Bl,
               float* __restrict__ C, int M, int K, int N,
               const int* __restrict__ degrm) {
    extern __shared__ __half sm[];
    uint32_t smbase = (uint32_t)__cvta_generic_to_shared(sm);
    __half* sAh = sm;
    __half* sAl = sAh + 128 * SMS;
    __half* sBh = sAl + 128 * SMS;
    __half* sBl = sBh + 128 * SMS;
    int t = threadIdx.x;
    int m0 = blockIdx.y * 128, n0 = blockIdx.x * 128;
    int w = t >> 5, lane = t & 31;
    int g = lane >> 2, tig = lane & 3;
    int wm = (w & 1) * 64, wn = (w >> 1) * 32;

    float acc[4][4][4];
#pragma unroll
    for (int i = 0; i < 4; i++)
#pragma unroll
        for (int j = 0; j < 4; j++)
#pragma unroll
            for (int k = 0; k < 4; k++) acc[i][j][k] = 0.f;

    for (int kc = 0; kc < K; kc += 64) {
        for (int idx = t; idx < 1024; idx += 256) {
            int r = idx >> 3, c = idx & 7;
            float4 f0 = make_float4(0.f, 0.f, 0.f, 0.f), f1 = f0;
            if (m0 + r < M) {
                size_t o = (size_t)(m0 + r) * K + kc + c * 8;
                f0 = *(const float4*)(A0 + o);
                f1 = *(const float4*)(A0 + o + 4);
                float4 q0 = *(const float4*)(A1 + o);
                float4 q1 = *(const float4*)(A1 + o + 4);
                f0.x += q0.x; f0.y += q0.y; f0.z += q0.z; f0.w += q0.w;
                f1.x += q1.x; f1.y += q1.y; f1.z += q1.z; f1.w += q1.w;
            }
            split4(f0, (__half2*)(sAh + r * SMS + c * 8), (__half2*)(sAl + r * SMS + c * 8));
            split4(f1, (__half2*)(sAh + r * SMS + c * 8 + 4), (__half2*)(sAl + r * SMS + c * 8 + 4));
        }
        for (int idx = t; idx < 2048; idx += 256) {
            int arr = idx >> 10, j = idx & 1023, r = j >> 3, c = j & 7;
            const __half* srcp = arr ? Bl : Bh;
            uint4 v = *(const uint4*)(srcp + (size_t)(n0 + r) * K + kc + c * 8);
            *(uint4*)((arr ? sBl : sBh) + r * SMS + c * 8) = v;
        }
        __syncthreads();
        compute_chunk(smbase, smbase + (uint32_t)(256 * SMS) * 2, (uint32_t)(128 * SMS) * 2,
                      wm, wn, lane, acc);
        __syncthreads();
    }
    gemm_epilogue(acc, C, M, N, m0, n0, wm, wn, g, tig, nullptr, nullptr, degrm, 0);
}

// ---------------- pooling ----------------
__global__ void scores_kernel(const float* __restrict__ h, const float* __restrict__ Wp,
                              const float* __restrict__ bp, const float* __restrict__ msk) {
    int warp = (blockIdx.x * blockDim.x + threadIdx.x) >> 5;
    int lane = threadIdx.x & 31;
    if (warp >= NN) return;
    const float* hr = h + (size_t)warp * FH;
    float z = 0.f;
#pragma unroll
    for (int j = 0; j < 8; j++) z = fmaf(hr[lane + 32 * j], Wp[lane + 32 * j], z);
#pragma unroll
    for (int off = 16; off; off >>= 1) z += __shfl_xor_sync(0xFFFFFFFFu, z, off);
    if (lane == 0) {
        z += bp[0];
        float s = 1.f / (1.f + expf(-z));
        g_scores[warp] = s;
        float kin = (msk && msk[warp] == 0.f) ? -1e9f : s;
        g_keys[warp] = f2k(kin);
    }
}

__global__ void topk_kernel(int K, int lvl) {
    __shared__ int hist[256];
    __shared__ unsigned s_pref;
    __shared__ int s_kr;
    int tid = threadIdx.x;
    if (tid == 0) { s_pref = 0u; s_kr = K; }
    const int NPAD = ((NN + 1023) / 1024) * 1024;
    for (int shift = 24; shift >= 0; shift -= 8) {
        if (tid < 256) hist[tid] = 0;
        __syncthreads();
        unsigned pref = s_pref;
        for (int i = tid; i < NPAD; i += 1024) {
            unsigned bucket = 0xFFFFFFFFu;
            if (i < NN) {
                unsigned k = g_keys[i];
                bool ok = (shift == 24) || ((k >> (shift + 8)) == (pref >> (shift + 8)));
                if (ok) bucket = (k >> shift) & 255u;
            }
            unsigned peers = __match_any_sync(0xFFFFFFFFu, bucket);
            if (bucket != 0xFFFFFFFFu) {
                int leader = __ffs(peers) - 1;
                if ((tid & 31) == leader) atomicAdd(&hist[bucket], __popc(peers));
            }
        }
        __syncthreads();
        if (tid == 0) {
            int kr = s_kr;
            for (int b = 255; b >= 0; b--) {
                int c = hist[b];
                if (c >= kr) { s_pref = pref | (((unsigned)b) << shift); break; }
                kr -= c;
            }
            s_kr = kr;
        }
        __syncthreads();
    }
    if (tid == 0) { g_prefix = s_pref; g_nact[lvl] = 0; }
}

__global__ void degm_kernel(const int* __restrict__ src, const int* __restrict__ dst,
                            int* __restrict__ degO, int* __restrict__ degI) {
    int e = blockIdx.x * blockDim.x + threadIdx.x;
    if (e >= NE) return;
    int s = src[e], d = dst[e];
    if (g_keys[s] >= g_prefix && g_keys[d] >= g_prefix) {
        atomicAdd(&degO[s], 1);
        atomicAdd(&degI[d], 1);
    }
}

__global__ void finact_kernel(const int* __restrict__ degO, const int* __restrict__ degI,
                              float* __restrict__ comb, float* __restrict__ dov,
                              float* __restrict__ divv, int* __restrict__ alist, int lvl) {
    int i = blockIdx.x * blockDim.x + threadIdx.x;
    if (i >= NN) return;
    float mo = rsqrtf((float)max(degO[i], 1));
    bool a = g_keys[i] >= g_prefix;
    comb[i] = a ? g_scores[i] * mo : 0.f;
    dov[i] = a ? mo : 0.f;
    divv[i] = rsqrtf((float)max(degI[i], 1));
    if (a) {
        int p = atomicAdd(&g_nact[lvl], 1);
        alist[p] = i;
    }
}

// ---------------- host orchestration ----------------
static inline void* sym(const void* s) {
    void* p = nullptr;
    cudaGetSymbolAddress(&p, (const void*)s);
    return p;
}

extern "C" void kernel_launch(void* const* d_in, const int* in_sizes, int n_in,
                              void* d_out, int out_size) {
    const float* features = (const float*)d_in[0];
    const int* src = (const int*)d_in[1];
    const int* dst = (const int*)d_in[2];
    const float* W_embed = (const float*)d_in[3];
    const float* b_embed = (const float*)d_in[4];
    const float* W_enc0 = (const float*)d_in[5];
    const float* b_enc0 = (const float*)d_in[6];
    const float* W_enc1 = (const float*)d_in[7];
    const float* b_enc1 = (const float*)d_in[8];
    const float* W_p0 = (const float*)d_in[9];
    const float* b_p0 = (const float*)d_in[10];
    const float* W_p1 = (const float*)d_in[11];
    const float* b_p1 = (const float*)d_in[12];
    const float* W_bot = (const float*)d_in[13];
    const float* b_bot = (const float*)d_in[14];
    const float* W_dec0 = (const float*)d_in[15];
    const float* b_dec0 = (const float*)d_in[16];
    const float* W_dec1 = (const float*)d_in[17];
    const float* b_dec1 = (const float*)d_in[18];
    float* out = (float*)d_out;

    float* p_xa   = (float*)sym(g_xa);
    float* p_h    = (float*)sym(g_h);
    float* p_hid0 = (float*)sym(g_hid0);
    float* p_hid1 = (float*)sym(g_hid1);
    float* p_hbot = (float*)sym(g_hbot);
    float* p_h4   = (float*)sym(g_h4);
    __half* p_xh  = (__half*)sym(g_xh);
    __half* p_xl  = (__half*)sym(g_xl);
    __half* p_wth = (__half*)sym(g_wth);
    __half* p_wtl = (__half*)sym(g_wtl);
    int* p_degout = (int*)sym(g_degout);
    int* p_degO1  = (int*)sym(g_degO1);
    int* p_degI1  = (int*)sym(g_degI1);
    int* p_degO2  = (int*)sym(g_degO2);
    int* p_degI2  = (int*)sym(g_degI2);
    float* p_comb1 = (float*)sym(g_comb1);
    float* p_dov1  = (float*)sym(g_dov1);
    float* p_div1  = (float*)sym(g_div1);
    float* p_comb2 = (float*)sym(g_comb2);
    float* p_dov2  = (float*)sym(g_dov2);
    float* p_div2  = (float*)sym(g_div2);
    int* p_al1 = (int*)sym(g_alist1);
    int* p_al2 = (int*)sym(g_alist2);

    cudaFuncSetAttribute(gemm_db_kernel, cudaFuncAttributeMaxDynamicSharedMemorySize, GEMM_SMEM_DB);
    cudaFuncSetAttribute(gemm_sb_kernel, cudaFuncAttributeMaxDynamicSharedMemorySize, GEMM_SMEM_SB);
    cudaFuncSetAttribute(fused_kernel, cudaFuncAttributeMaxDynamicSharedMemorySize, FUSED_SMEM);

    const int TB = 256;
    const int NB_N = (NN + TB - 1) / TB;
    const int NB_E = (NE + TB - 1) / TB;
    dim3 gFull256(2, (NN + 127) / 128);
    dim3 gFull128(1, (NN + 127) / 128);
    auto wgrid = [](int n) { return (n + 7) / 8; };
    const int FB_NN = (NN + 127) / 128;  // 391
    const int FB_K1 = (K1 + 127) / 128;  // 196
    const int FB_K2 = (K2 + 127) / 128;  // 98

    // prep + CSR build
    prep_kernel<<<(327680 + TB - 1) / TB, TB>>>(W_embed, W_enc0, W_enc1, W_bot, W_dec0, W_dec1);
    hist_kernel<<<NB_E, TB>>>(src, dst);
    scan1_kernel<<<NSCAN, 1024>>>();
    scan3_kernel<<<NB_N, TB>>>();
    scatter_kernel<<<NB_E, TB>>>(src, dst);

    // L0: standalone agg (F=128) + db GEMM 128->256
    agg_half_kernel<<<wgrid(NN), TB>>>(features, p_degout, p_xh, p_xl);
    gemm_db_kernel<<<gFull256, 256, GEMM_SMEM_DB>>>(p_xh, p_xl, p_wth + WO_EMB, p_wtl + WO_EMB,
                                                    p_h, NN, FI, FH, b_embed, 1);

    // L1: fused agg+GEMM (full graph) -> hid0
    fused_kernel<<<FB_NN, 512, FUSED_SMEM>>>(p_h, nullptr, nullptr, p_degout, nullptr, nullptr,
                                             p_wth + WO_ENC0, p_wtl + WO_ENC0, p_hid0,
                                             NN, b_enc0, 1);

    // pool0
    scores_kernel<<<(NN + 7) / 8, TB>>>(p_hid0, W_p0, b_p0, nullptr);
    topk_kernel<<<1, 1024>>>(K1, 0);
    degm_kernel<<<NB_E, TB>>>(src, dst, p_degO1, p_degI1);
    finact_kernel<<<NB_N, TB>>>(p_degO1, p_degI1, p_comb1, p_dov1, p_div1, p_al1, 0);

    // L2: fused (compact M=K1) -> hid1
    fused_kernel<<<FB_K1, 512, FUSED_SMEM>>>(p_hid0, nullptr, p_comb1, nullptr, p_div1, p_al1,
                                             p_wth + WO_ENC1, p_wtl + WO_ENC1, p_hid1,
                                             K1, b_enc1, 1);

    // pool1
    scores_kernel<<<(NN + 7) / 8, TB>>>(p_hid1, W_p1, b_p1, p_dov1);
    topk_kernel<<<1, 1024>>>(K2, 1);
    degm_kernel<<<NB_E, TB>>>(src, dst, p_degO2, p_degI2);
    finact_kernel<<<NB_N, TB>>>(p_degO2, p_degI2, p_comb2, p_dov2, p_div2, p_al2, 1);

    // L3: fused (compact M=K2) -> hbot
    fused_kernel<<<FB_K2, 512, FUSED_SMEM>>>(p_hid1, nullptr, p_comb2, nullptr, p_div2, p_al2,
                                             p_wth + WO_BOT, p_wtl + WO_BOT, p_hbot,
                                             K2, b_bot, 1);

    // L4: fused (compact M=K1, skip add x2=hid1) -> h4
    fused_kernel<<<FB_K1, 512, FUSED_SMEM>>>(p_hbot, p_hid1, p_dov1, nullptr, p_div1, p_al1,
                                             p_wth + WO_DEC0, p_wtl + WO_DEC0, p_h4,
                                             K1, b_dec0, 1);

    // L5: fused (h4+hid0) split-on-load GEMM (256->128, rowmul); then agg -> out
    gemm_sb_kernel<<<gFull128, 256, GEMM_SMEM_SB>>>(p_h4, p_hid0, p_wth + WO_DEC1,
                                                    p_wtl + WO_DEC1, p_xa, NN, FH, FI,
                                                    p_degout);
    agg_out_kernel<<<wgrid(NN), TB>>>(p_xa, b_dec1, out);
}

// round 9
// speedup vs baseline: 1.1459x; 1.1459x over previous
#include <cuda_runtime.h>
#include <cuda_fp16.h>
#include <math.h>
#include <stdint.h>

#define NN 50000
#define NE 800000
#define FI 128
#define FH 256
#define K1 25000
#define K2 12500
#define NSCAN 49  // ceil(NN/1024)

// ---------------- scratch (device globals; zero-init, allocation-free) -----
__device__ __align__(16) float g_xa[NN * FH];    // L5 gemm out
__device__ __align__(16) float g_h[NN * FH];     // L0 gemm out / L4 presum
__device__ __align__(16) float g_hid0[NN * FH];  // L1 out (full)
__device__ __align__(16) float g_hid1[NN * FH];  // L2 out (scattered; else 0)
__device__ __align__(16) float g_hbot[NN * FH];  // L3 out (scattered; else 0)
__device__ __align__(16) float g_h4[NN * FH];    // L4 out (scattered; else 0)
__device__ __align__(16) __half g_xh[NN * FH];   // gemm A hi
__device__ __align__(16) __half g_xl[NN * FH];   // gemm A lo
__device__ __align__(16) __half g_wth[327680];   // weights hi (transposed)
__device__ __align__(16) __half g_wtl[327680];   // weights lo
__device__ int g_degout[NN];
__device__ int g_degO1[NN], g_degI1[NN], g_degO2[NN], g_degI2[NN];
__device__ float g_comb1[NN], g_dov1[NN], g_div1[NN];
__device__ float g_comb2[NN], g_dov2[NN], g_div2[NN];
__device__ float g_scores[NN];
__device__ unsigned g_keys[NN];
__device__ int g_rowstart[NN + 1];
__device__ int g_rowoff[NN];
__device__ int g_csrsrc[NE];
__device__ int g_alist1[NN], g_alist2[NN];
__device__ int g_nact[2];
__device__ unsigned g_prefix;
__device__ int g_bsum[64];

#define WO_EMB  0
#define WO_ENC0 32768
#define WO_ENC1 98304
#define WO_BOT  163840
#define WO_DEC0 229376
#define WO_DEC1 294912

__device__ __forceinline__ unsigned f2k(float f) {
    unsigned u = __float_as_uint(f);
    return (u & 0x80000000u) ? ~u : (u | 0x80000000u);
}
__device__ __forceinline__ void split4(float4 v, __half2* ph, __half2* pl) {
    __half h0 = __float2half_rn(v.x), h1 = __float2half_rn(v.y);
    __half h2 = __float2half_rn(v.z), h3 = __float2half_rn(v.w);
    __half l0 = __float2half_rn(v.x - __half2float(h0));
    __half l1 = __float2half_rn(v.y - __half2float(h1));
    __half l2 = __float2half_rn(v.z - __half2float(h2));
    __half l3 = __float2half_rn(v.w - __half2float(h3));
    ph[0] = __halves2half2(h0, h1); ph[1] = __halves2half2(h2, h3);
    pl[0] = __halves2half2(l0, l1); pl[1] = __halves2half2(l2, l3);
}

// ---------------- prep ----------------
__global__ void prep_kernel(const float* __restrict__ We, const float* __restrict__ W0,
                            const float* __restrict__ W1, const float* __restrict__ Wb,
                            const float* __restrict__ Wd0, const float* __restrict__ Wd1) {
    int i = blockIdx.x * blockDim.x + threadIdx.x;
    if (i < NN) {
        g_rowoff[i] = 0; g_degout[i] = 0;
        g_degO1[i] = 0; g_degI1[i] = 0;
        g_degO2[i] = 0; g_degI2[i] = 0;
    }
    if (i == 0) { g_nact[0] = 0; g_nact[1] = 0; g_rowstart[NN] = NE; }
    float w; int o;
    if (i < 32768) {
        int k = i >> 8, n = i & 255;
        w = We[i]; o = WO_EMB + n * 128 + k;
    } else if (i < 98304) {
        int j = i - 32768; int k = j >> 8, n = j & 255;
        w = W0[j]; o = WO_ENC0 + n * 256 + k;
    } else if (i < 163840) {
        int j = i - 98304; int k = j >> 8, n = j & 255;
        w = W1[j]; o = WO_ENC1 + n * 256 + k;
    } else if (i < 229376) {
        int j = i - 163840; int k = j >> 8, n = j & 255;
        w = Wb[j]; o = WO_BOT + n * 256 + k;
    } else if (i < 294912) {
        int j = i - 229376; int k = j >> 8, n = j & 255;
        w = Wd0[j]; o = WO_DEC0 + n * 256 + k;
    } else if (i < 327680) {
        int j = i - 294912; int k = j >> 7, n = j & 127;
        w = Wd1[j]; o = WO_DEC1 + n * 256 + k;
    } else return;
    __half h = __float2half_rn(w);
    g_wth[o] = h;
    g_wtl[o] = __float2half_rn(w - __half2float(h));
}

// ---------------- CSR build ----------------
__global__ void hist_kernel(const int* __restrict__ src, const int* __restrict__ dst) {
    int e = blockIdx.x * blockDim.x + threadIdx.x;
    if (e < NE) {
        atomicAdd(&g_rowoff[dst[e]], 1);
        atomicAdd(&g_degout[src[e]], 1);
    }
}
__global__ void scan1_kernel() {
    int b = blockIdx.x, t = threadIdx.x;
    int i = b * 1024 + t;
    int v = (i < NN) ? g_rowoff[i] : 0;
    int lane = t & 31, wid = t >> 5;
    int x = v;
#pragma unroll
    for (int off = 1; off < 32; off <<= 1) {
        int y = __shfl_up_sync(0xFFFFFFFFu, x, off);
        if (lane >= off) x += y;
    }
    __shared__ int ws[32];
    if (lane == 31) ws[wid] = x;
    __syncthreads();
    if (wid == 0) {
        int y = ws[lane];
#pragma unroll
        for (int off = 1; off < 32; off <<= 1) {
            int z = __shfl_up_sync(0xFFFFFFFFu, y, off);
            if (lane >= off) y += z;
        }
        ws[lane] = y;
    }
    __syncthreads();
    int base = wid ? ws[wid - 1] : 0;
    if (i < NN) g_rowstart[i] = base + x - v;
    if (t == 1023) g_bsum[b] = base + x;
}
__global__ void scan3_kernel() {
    __shared__ int boff[NSCAN + 1];
    int t = threadIdx.x;
    if (t < NSCAN) boff[t + 1] = g_bsum[t];
    __syncthreads();
    if (t == 0) {
        boff[0] = 0;
        for (int b = 1; b <= NSCAN; b++) boff[b] += boff[b - 1];
    }
    __syncthreads();
    int i = blockIdx.x * blockDim.x + t;
    if (i < NN) {
        int rs = g_rowstart[i] + boff[i >> 10];
        g_rowstart[i] = rs;
        g_rowoff[i] = rs;
    }
}
__global__ void scatter_kernel(const int* __restrict__ src, const int* __restrict__ dst) {
    int e = blockIdx.x * blockDim.x + threadIdx.x;
    if (e < NE) {
        int pos = atomicAdd(&g_rowoff[dst[e]], 1);
        g_csrsrc[pos] = src[e];
    }
}

// ---------------- CSR aggregation: 1 warp per node ----------------
__global__ void agg_half_kernel(const float* __restrict__ x,
                                const float* __restrict__ smul, const int* __restrict__ degsrc,
                                const float* __restrict__ divv, const int* __restrict__ alist,
                                __half* __restrict__ oh, __half* __restrict__ ol,
                                int F, int nnodes) {
    int wid = (blockIdx.x * blockDim.x + threadIdx.x) >> 5;
    if (wid >= nnodes) return;
    int lane = threadIdx.x & 31;
    int node = alist ? alist[wid] : wid;
    int s = g_rowstart[node], e = g_rowstart[node + 1];
    int f4 = F >> 2;
    bool wide = (f4 == 64);
    float4 a0 = make_float4(0.f, 0.f, 0.f, 0.f);
    float4 a1 = make_float4(0.f, 0.f, 0.f, 0.f);
    for (int b = s; b < e; b += 32) {
        int nn = min(32, e - b);
        int si = 0; float sc = 0.f;
        if (lane < nn) {
            si = g_csrsrc[b + lane];
            if (smul) sc = smul[si];
            else if (degsrc) sc = rsqrtf((float)max(degsrc[si], 1));
            else sc = 1.f;
        }
        for (int k = 0; k < nn; k++) {
            int sik = __shfl_sync(0xFFFFFFFFu, si, k);
            float sck = __shfl_sync(0xFFFFFFFFu, sc, k);
            if (sck != 0.f) {
                const float4* xp = (const float4*)x + (size_t)sik * f4 + lane;
                float4 v = xp[0];
                a0.x = fmaf(v.x, sck, a0.x); a0.y = fmaf(v.y, sck, a0.y);
                a0.z = fmaf(v.z, sck, a0.z); a0.w = fmaf(v.w, sck, a0.w);
                if (wide) {
                    float4 v1 = xp[32];
                    a1.x = fmaf(v1.x, sck, a1.x); a1.y = fmaf(v1.y, sck, a1.y);
                    a1.z = fmaf(v1.z, sck, a1.z); a1.w = fmaf(v1.w, sck, a1.w);
                }
            }
        }
    }
    float dv = divv ? divv[node] : rsqrtf((float)max(e - s, 1));
    a0.x *= dv; a0.y *= dv; a0.z *= dv; a0.w *= dv;
    int wrow = alist ? wid : node;
    size_t o = (size_t)wrow * F + lane * 4;
    split4(a0, (__half2*)(oh + o), (__half2*)(ol + o));
    if (wide) {
        a1.x *= dv; a1.y *= dv; a1.z *= dv; a1.w *= dv;
        split4(a1, (__half2*)(oh + o + 128), (__half2*)(ol + o + 128));
    }
}

__global__ void agg_out_kernel(const float* __restrict__ x, const float* __restrict__ bias,
                               float* __restrict__ out) {
    int wid = (blockIdx.x * blockDim.x + threadIdx.x) >> 5;
    if (wid >= NN) return;
    int lane = threadIdx.x & 31;
    int s = g_rowstart[wid], e = g_rowstart[wid + 1];
    float4 acc = make_float4(0.f, 0.f, 0.f, 0.f);
    for (int b = s; b < e; b += 32) {
        int nn = min(32, e - b);
        int si = 0;
        if (lane < nn) si = g_csrsrc[b + lane];
        for (int k = 0; k < nn; k++) {
            int sik = __shfl_sync(0xFFFFFFFFu, si, k);
            float4 v = ((const float4*)x)[(size_t)sik * 32 + lane];
            acc.x += v.x; acc.y += v.y; acc.z += v.z; acc.w += v.w;
        }
    }
    float dv = rsqrtf((float)max(e - s, 1));
    float4 bb = ((const float4*)bias)[lane];
    acc.x = fmaf(acc.x, dv, bb.x); acc.y = fmaf(acc.y, dv, bb.y);
    acc.z = fmaf(acc.z, dv, bb.z); acc.w = fmaf(acc.w, dv, bb.w);
    ((float4*)out)[(size_t)wid * 32 + lane] = acc;
}

// L4 pre-sum over ACTIVE rows only: h[row] = hbot[row] + hid1[row], row in alist1
__global__ void presum_kernel(const float* __restrict__ a, const float* __restrict__ b,
                              const int* __restrict__ alist, float* __restrict__ o, int nact) {
    int idx = blockIdx.x * blockDim.x + threadIdx.x;
    if (idx >= nact * 64) return;
    int j = idx >> 6, f = idx & 63;
    size_t off = (size_t)alist[j] * 64 + f;
    float4 va = ((const float4*)a)[off];
    float4 vb = ((const float4*)b)[off];
    va.x += vb.x; va.y += vb.y; va.z += vb.z; va.w += vb.w;
    ((float4*)o)[off] = va;
}

// ---------------- HMMA fp16-split GEMM (ldmatrix, single-buffer, occ 2) ----
#define SMS 72
#define GEMM_SMEM (4 * 128 * SMS * 2)

#define MMA168(d, a, b) \
    asm volatile( \
        "mma.sync.aligned.m16n8k16.row.col.f32.f16.f16.f32 " \
        "{%0,%1,%2,%3}, {%4,%5,%6,%7}, {%8,%9}, {%0,%1,%2,%3};" \
        : "+f"((d)[0]), "+f"((d)[1]), "+f"((d)[2]), "+f"((d)[3]) \
        : "r"((a)[0]), "r"((a)[1]), "r"((a)[2]), "r"((a)[3]), \
          "r"((b)[0]), "r"((b)[1]))

__device__ __forceinline__ void ldsm4(uint32_t addr, uint32_t* r) {
    asm volatile("ldmatrix.sync.aligned.m8n8.x4.shared.b16 {%0,%1,%2,%3}, [%4];"
                 : "=r"(r[0]), "=r"(r[1]), "=r"(r[2]), "=r"(r[3]) : "r"(addr));
}

// one 64-wide K chunk via ldmatrix. layout: Ah@0, Al@+128*SMS, Bh@+256*SMS, Bl@+384*SMS (halfs)
__device__ __forceinline__ void compute_chunk(uint32_t sb, int wm, int wn, int lane,
                                              float acc[4][4][4]) {
    const uint32_t bAh = sb;
    const uint32_t bAl = sb + 128 * SMS * 2;
    const uint32_t bBh = sb + 256 * SMS * 2;
    const uint32_t bBl = sb + 384 * SMS * 2;
    uint32_t aOff = (uint32_t)((wm + (lane & 15)) * SMS + (lane >> 4) * 8) * 2;
    uint32_t bOff = (uint32_t)((wn + ((lane >> 4) & 1) * 8 + (lane & 7)) * SMS +
                               ((lane >> 3) & 1) * 8) * 2;
#pragma unroll
    for (int ks = 0; ks < 4; ks++) {
        uint32_t kb2 = (uint32_t)ks * 32;
        uint32_t ar[4][4], br[4][2], bl[4][2];
#pragma unroll
        for (int mi = 0; mi < 4; mi++)
            ldsm4(bAh + aOff + mi * (16 * SMS * 2) + kb2, ar[mi]);
#pragma unroll
        for (int p = 0; p < 2; p++) {
            uint32_t r4[4];
            ldsm4(bBh + bOff + p * (16 * SMS * 2) + kb2, r4);
            br[2 * p][0] = r4[0]; br[2 * p][1] = r4[1];
            br[2 * p + 1][0] = r4[2]; br[2 * p + 1][1] = r4[3];
            ldsm4(bBl + bOff + p * (16 * SMS * 2) + kb2, r4);
            bl[2 * p][0] = r4[0]; bl[2 * p][1] = r4[1];
            bl[2 * p + 1][0] = r4[2]; bl[2 * p + 1][1] = r4[3];
        }
#pragma unroll
        for (int mi = 0; mi < 4; mi++)
#pragma unroll
            for (int ni = 0; ni < 4; ni++) {
                MMA168(acc[mi][ni], ar[mi], br[ni]);
                MMA168(acc[mi][ni], ar[mi], bl[ni]);
            }
#pragma unroll
        for (int mi = 0; mi < 4; mi++)
            ldsm4(bAl + aOff + mi * (16 * SMS * 2) + kb2, ar[mi]);
#pragma unroll
        for (int mi = 0; mi < 4; mi++)
#pragma unroll
            for (int ni = 0; ni < 4; ni++)
                MMA168(acc[mi][ni], ar[mi], br[ni]);
    }
}

__device__ __forceinline__ void gemm_epilogue(float acc[4][4][4], float* C, int M, int N,
                                              int m0, int n0, int wm, int wn, int g, int tig,
                                              const int* alist, const float* bias,
                                              const int* degrm, int act) {
#pragma unroll
    for (int mi = 0; mi < 4; mi++) {
#pragma unroll
        for (int half8 = 0; half8 < 2; half8++) {
            int lrow = m0 + wm + mi * 16 + g + half8 * 8;
            if (lrow >= M) continue;
            int grow = alist ? alist[lrow] : lrow;
            float rm = degrm ? rsqrtf((float)max(degrm[grow], 1)) : 1.f;
#pragma unroll
            for (int ni = 0; ni < 4; ni++) {
                int col = n0 + wn + ni * 8 + tig * 2;
                float v0 = acc[mi][ni][half8 * 2 + 0];
                float v1 = acc[mi][ni][half8 * 2 + 1];
                if (bias) { v0 += bias[col]; v1 += bias[col + 1]; }
                if (act) { v0 = fmaxf(v0, 0.f); v1 = fmaxf(v1, 0.f); }
                v0 *= rm; v1 *= rm;
                *(float2*)(C + (size_t)grow * N + col) = make_float2(v0, v1);
            }
        }
    }
}

// AHALF=1: A pre-split (Ah/Al). AHALF=0: A = A0 (+A1), split on load.
template <int AHALF>
__global__ void __launch_bounds__(256, 2)
gemm_kernel(const __half* __restrict__ Ah, const __half* __restrict__ Al,
            const float* __restrict__ A0, const float* __restrict__ A1,
            const __half* __restrict__ Bh, const __half* __restrict__ Bl,
            float* __restrict__ C, int M, int K, int N,
            const int* __restrict__ alist, const float* __restrict__ bias,
            const int* __restrict__ degrm, int act) {
    extern __shared__ __half sm[];
    uint32_t smbase = (uint32_t)__cvta_generic_to_shared(sm);
    __half* sAh = sm;
    __half* sAl = sAh + 128 * SMS;
    __half* sBh = sAl + 128 * SMS;
    __half* sBl = sBh + 128 * SMS;
    int t = threadIdx.x;
    int m0 = blockIdx.y * 128, n0 = blockIdx.x * 128;
    int w = t >> 5, lane = t & 31;
    int g = lane >> 2, tig = lane & 3;
    int wm = (w & 1) * 64, wn = (w >> 1) * 32;

    float acc[4][4][4];
#pragma unroll
    for (int i = 0; i < 4; i++)
#pragma unroll
        for (int j = 0; j < 4; j++)
#pragma unroll
            for (int k = 0; k < 4; k++) acc[i][j][k] = 0.f;

    for (int kc = 0; kc < K; kc += 64) {
        if (AHALF) {
            for (int idx = t; idx < 2048; idx += 256) {
                int arr = idx >> 10, j = idx & 1023, r = j >> 3, c = j & 7;
                const __half* srcp = arr ? Al : Ah;
                uint4 v = make_uint4(0, 0, 0, 0);
                if (m0 + r < M) v = *(const uint4*)(srcp + (size_t)(m0 + r) * K + kc + c * 8);
                *(uint4*)((arr ? sAl : sAh) + r * SMS + c * 8) = v;
            }
        } else {
            for (int idx = t; idx < 1024; idx += 256) {
                int r = idx >> 3, c = idx & 7;
                float4 f0 = make_float4(0.f, 0.f, 0.f, 0.f), f1 = f0;
                if (m0 + r < M) {
                    size_t o = (size_t)(m0 + r) * K + kc + c * 8;
                    f0 = *(const float4*)(A0 + o);
                    f1 = *(const float4*)(A0 + o + 4);
                    float4 q0 = *(const float4*)(A1 + o);
                    float4 q1 = *(const float4*)(A1 + o + 4);
                    f0.x += q0.x; f0.y += q0.y; f0.z += q0.z; f0.w += q0.w;
                    f1.x += q1.x; f1.y += q1.y; f1.z += q1.z; f1.w += q1.w;
                }
                split4(f0, (__half2*)(sAh + r * SMS + c * 8), (__half2*)(sAl + r * SMS + c * 8));
                split4(f1, (__half2*)(sAh + r * SMS + c * 8 + 4), (__half2*)(sAl + r * SMS + c * 8 + 4));
            }
        }
        for (int idx = t; idx < 2048; idx += 256) {
            int arr = idx >> 10, j = idx & 1023, r = j >> 3, c = j & 7;
            const __half* srcp = arr ? Bl : Bh;
            uint4 v = *(const uint4*)(srcp + (size_t)(n0 + r) * K + kc + c * 8);
            *(uint4*)((arr ? sBl : sBh) + r * SMS + c * 8) = v;
        }
        __syncthreads();
        compute_chunk(smbase, wm, wn, lane, acc);
        __syncthreads();
    }
    gemm_epilogue(acc, C, M, N, m0, n0, wm, wn, g, tig, alist, bias, degrm, act);
}

// ---------------- pooling ----------------
__global__ void scores_kernel(const float* __restrict__ h, const float* __restrict__ Wp,
                              const float* __restrict__ bp, const float* __restrict__ msk) {
    int warp = (blockIdx.x * blockDim.x + threadIdx.x) >> 5;
    int lane = threadIdx.x & 31;
    if (warp >= NN) return;
    const float* hr = h + (size_t)warp * FH;
    float z = 0.f;
#pragma unroll
    for (int j = 0; j < 8; j++) z = fmaf(hr[lane + 32 * j], Wp[lane + 32 * j], z);
#pragma unroll
    for (int off = 16; off; off >>= 1) z += __shfl_xor_sync(0xFFFFFFFFu, z, off);
    if (lane == 0) {
        z += bp[0];
        float s = 1.f / (1.f + expf(-z));
        g_scores[warp] = s;
        float kin = (msk && msk[warp] == 0.f) ? -1e9f : s;
        g_keys[warp] = f2k(kin);
    }
}

__global__ void topk_kernel(int K, int lvl) {
    __shared__ int hist[256];
    __shared__ unsigned s_pref;
    __shared__ int s_kr;
    int tid = threadIdx.x;
    if (tid == 0) { s_pref = 0u; s_kr = K; }
    const int NPAD = ((NN + 1023) / 1024) * 1024;
    for (int shift = 24; shift >= 0; shift -= 8) {
        if (tid < 256) hist[tid] = 0;
        __syncthreads();
        unsigned pref = s_pref;
        for (int i = tid; i < NPAD; i += 1024) {
            unsigned bucket = 0xFFFFFFFFu;
            if (i < NN) {
                unsigned k = g_keys[i];
                bool ok = (shift == 24) || ((k >> (shift + 8)) == (pref >> (shift + 8)));
                if (ok) bucket = (k >> shift) & 255u;
            }
            unsigned peers = __match_any_sync(0xFFFFFFFFu, bucket);
            if (bucket != 0xFFFFFFFFu) {
                int leader = __ffs(peers) - 1;
                if ((tid & 31) == leader) atomicAdd(&hist[bucket], __popc(peers));
            }
        }
        __syncthreads();
        if (tid == 0) {
            int kr = s_kr;
            for (int b = 255; b >= 0; b--) {
                int c = hist[b];
                if (c >= kr) { s_pref = pref | (((unsigned)b) << shift); break; }
                kr -= c;
            }
            s_kr = kr;
        }
        __syncthreads();
    }
    if (tid == 0) { g_prefix = s_pref; g_nact[lvl] = 0; }
}

__global__ void degm_kernel(const int* __restrict__ src, const int* __restrict__ dst,
                            int* __restrict__ degO, int* __restrict__ degI) {
    int e = blockIdx.x * blockDim.x + threadIdx.x;
    if (e >= NE) return;
    int s = src[e], d = dst[e];
    if (g_keys[s] >= g_prefix && g_keys[d] >= g_prefix) {
        atomicAdd(&degO[s], 1);
        atomicAdd(&degI[d], 1);
    }
}

__global__ void finact_kernel(const int* __restrict__ degO, const int* __restrict__ degI,
                              float* __restrict__ comb, float* __restrict__ dov,
                              float* __restrict__ divv, int* __restrict__ alist, int lvl) {
    int i = blockIdx.x * blockDim.x + threadIdx.x;
    if (i >= NN) return;
    float mo = rsqrtf((float)max(degO[i], 1));
    bool a = g_keys[i] >= g_prefix;
    comb[i] = a ? g_scores[i] * mo : 0.f;
    dov[i] = a ? mo : 0.f;
    divv[i] = rsqrtf((float)max(degI[i], 1));
    if (a) {
        int p = atomicAdd(&g_nact[lvl], 1);
        alist[p] = i;
    }
}

// ---------------- host orchestration ----------------
static inline void* sym(const void* s) {
    void* p = nullptr;
    cudaGetSymbolAddress(&p, (const void*)s);
    return p;
}

extern "C" void kernel_launch(void* const* d_in, const int* in_sizes, int n_in,
                              void* d_out, int out_size) {
    const float* features = (const float*)d_in[0];
    const int* src = (const int*)d_in[1];
    const int* dst = (const int*)d_in[2];
    const float* W_embed = (const float*)d_in[3];
    const float* b_embed = (const float*)d_in[4];
    const float* W_enc0 = (const float*)d_in[5];
    const float* b_enc0 = (const float*)d_in[6];
    const float* W_enc1 = (const float*)d_in[7];
    const float* b_enc1 = (const float*)d_in[8];
    const float* W_p0 = (const float*)d_in[9];
    const float* b_p0 = (const float*)d_in[10];
    const float* W_p1 = (const float*)d_in[11];
    const float* b_p1 = (const float*)d_in[12];
    const float* W_bot = (const float*)d_in[13];
    const float* b_bot = (const float*)d_in[14];
    const float* W_dec0 = (const float*)d_in[15];
    const float* b_dec0 = (const float*)d_in[16];
    const float* W_dec1 = (const float*)d_in[17];
    const float* b_dec1 = (const float*)d_in[18];
    float* out = (float*)d_out;

    float* p_xa   = (float*)sym(g_xa);
    float* p_h    = (float*)sym(g_h);
    float* p_hid0 = (float*)sym(g_hid0);
    float* p_hid1 = (float*)sym(g_hid1);
    float* p_hbot = (float*)sym(g_hbot);
    float* p_h4   = (float*)sym(g_h4);
    __half* p_xh  = (__half*)sym(g_xh);
    __half* p_xl  = (__half*)sym(g_xl);
    __half* p_wth = (__half*)sym(g_wth);
    __half* p_wtl = (__half*)sym(g_wtl);
    int* p_degout = (int*)sym(g_degout);
    int* p_degO1  = (int*)sym(g_degO1);
    int* p_degI1  = (int*)sym(g_degI1);
    int* p_degO2  = (int*)sym(g_degO2);
    int* p_degI2  = (int*)sym(g_degI2);
    float* p_comb1 = (float*)sym(g_comb1);
    float* p_dov1  = (float*)sym(g_dov1);
    float* p_div1  = (float*)sym(g_div1);
    float* p_comb2 = (float*)sym(g_comb2);
    float* p_dov2  = (float*)sym(g_dov2);
    float* p_div2  = (float*)sym(g_div2);
    int* p_al1 = (int*)sym(g_alist1);
    int* p_al2 = (int*)sym(g_alist2);

    cudaFuncSetAttribute(gemm_kernel<1>, cudaFuncAttributeMaxDynamicSharedMemorySize, GEMM_SMEM);
    cudaFuncSetAttribute(gemm_kernel<0>, cudaFuncAttributeMaxDynamicSharedMemorySize, GEMM_SMEM);

    const int TB = 256;
    const int NB_N = (NN + TB - 1) / TB;
    const int NB_E = (NE + TB - 1) / TB;
    dim3 gFull256(2, (NN + 127) / 128);
    dim3 gFull128(1, (NN + 127) / 128);
    dim3 gK1(2, (K1 + 127) / 128);
    dim3 gK2(2, (K2 + 127) / 128);
    auto wgrid = [](int n) { return (n + 7) / 8; };

    // prep + CSR build
    prep_kernel<<<(327680 + TB - 1) / TB, TB>>>(W_embed, W_enc0, W_enc1, W_bot, W_dec0, W_dec1);
    hist_kernel<<<NB_E, TB>>>(src, dst);
    scan1_kernel<<<NSCAN, 1024>>>();
    scan3_kernel<<<NB_N, TB>>>();
    scatter_kernel<<<NB_E, TB>>>(src, dst);

    // L0
    agg_half_kernel<<<wgrid(NN), TB>>>(features, nullptr, p_degout, nullptr, nullptr,
                                       p_xh, p_xl, FI, NN);
    gemm_kernel<1><<<gFull256, 256, GEMM_SMEM>>>(p_xh, p_xl, nullptr, nullptr,
                                                 p_wth + WO_EMB, p_wtl + WO_EMB, p_h,
                                                 NN, FI, FH, nullptr, b_embed, nullptr, 1);

    // L1
    agg_half_kernel<<<wgrid(NN), TB>>>(p_h, nullptr, p_degout, nullptr, nullptr,
                                       p_xh, p_xl, FH, NN);
    gemm_kernel<1><<<gFull256, 256, GEMM_SMEM>>>(p_xh, p_xl, nullptr, nullptr,
                                                 p_wth + WO_ENC0, p_wtl + WO_ENC0, p_hid0,
                                                 NN, FH, FH, nullptr, b_enc0, nullptr, 1);

    // pool0
    scores_kernel<<<(NN + 7) / 8, TB>>>(p_hid0, W_p0, b_p0, nullptr);
    topk_kernel<<<1, 1024>>>(K1, 0);
    degm_kernel<<<NB_E, TB>>>(src, dst, p_degO1, p_degI1);
    finact_kernel<<<NB_N, TB>>>(p_degO1, p_degI1, p_comb1, p_dov1, p_div1, p_al1, 0);

    // L2
    agg_half_kernel<<<wgrid(K1), TB>>>(p_hid0, p_comb1, nullptr, p_div1, p_al1,
                                       p_xh, p_xl, FH, K1);
    gemm_kernel<1><<<gK1, 256, GEMM_SMEM>>>(p_xh, p_xl, nullptr, nullptr,
                                            p_wth + WO_ENC1, p_wtl + WO_ENC1, p_hid1,
                                            K1, FH, FH, p_al1, b_enc1, nullptr, 1);

    // pool1
    scores_kernel<<<(NN + 7) / 8, TB>>>(p_hid1, W_p1, b_p1, p_dov1);
    topk_kernel<<<1, 1024>>>(K2, 1);
    degm_kernel<<<NB_E, TB>>>(src, dst, p_degO2, p_degI2);
    finact_kernel<<<NB_N, TB>>>(p_degO2, p_degI2, p_comb2, p_dov2, p_div2, p_al2, 1);

    // L3
    agg_half_kernel<<<wgrid(K2), TB>>>(p_hid1, p_comb2, nullptr, p_div2, p_al2,
                                       p_xh, p_xl, FH, K2);
    gemm_kernel<1><<<gK2, 256, GEMM_SMEM>>>(p_xh, p_xl, nullptr, nullptr,
                                            p_wth + WO_BOT, p_wtl + WO_BOT, p_hbot,
                                            K2, FH, FH, p_al2, b_bot, nullptr, 1);

    // L4: presum (hbot+hid1) over active rows only, then single-array gather
    presum_kernel<<<(K1 * 64 + TB - 1) / TB, TB>>>(p_hbot, p_hid1, p_al1, p_h, K1);
    agg_half_kernel<<<wgrid(K1), TB>>>(p_h, p_dov1, nullptr, p_div1, p_al1,
                                       p_xh, p_xl, FH, K1);
    gemm_kernel<1><<<gK1, 256, GEMM_SMEM>>>(p_xh, p_xl, nullptr, nullptr,
                                            p_wth + WO_DEC0, p_wtl + WO_DEC0, p_h4,
                                            K1, FH, FH, p_al1, b_dec0, nullptr, 1);

    // L5: fused (h4+hid0) split-on-load GEMM (256->128, rowmul); then agg -> out
    gemm_kernel<0><<<gFull128, 256, GEMM_SMEM>>>(nullptr, nullptr, p_h4, p_hid0,
                                                 p_wth + WO_DEC1, p_wtl + WO_DEC1, p_xa,
                                                 NN, FH, FI, nullptr, nullptr, p_degout, 0);
    agg_out_kernel<<<wgrid(NN), TB>>>(p_xa, b_dec1, out);
}